// round 5
// baseline (speedup 1.0000x reference)
#include <cuda_runtime.h>

// DyDepthwiseConvAtten: B=1024, N=100, C=256, K=3  (rows = 102400)
// Round 4: HALF-WARP rows. Each warp = 2 rows; lanes 0-15 own row A
// (16 channels/lane), lanes 16-31 own row B. Width-16 shfl butterflies
// (4 stages, shared issue across 2 rows) and hardware-deduped invariant
// loads (both half-warps read identical Ww/gamma/beta addresses).

#define C_DIM 256
#define LN_EPS 1e-5f
#define WARPS_PER_CTA 8
#define ROWS_PER_CTA (WARPS_PER_CTA * 2)   // 16

__global__ __launch_bounds__(WARPS_PER_CTA * 32)
void dydw_atten_kernel(const float* __restrict__ q,
                       const float* __restrict__ v,
                       const float* __restrict__ Ww,   // [3,256]
                       const float* __restrict__ bw,   // [3]
                       const float* __restrict__ gamma,
                       const float* __restrict__ beta,
                       float* __restrict__ out) {
    const int lane = threadIdx.x & 31;
    const int wrp  = threadIdx.x >> 5;
    const int sub  = lane & 15;            // lane within half-warp
    const int half = lane >> 4;            // which row of the pair
    const int row  = blockIdx.x * ROWS_PER_CTA + wrp * 2 + half;

    const int    coff = sub * 16;          // this thread's 16 channels
    const size_t base = (size_t)row * C_DIM + coff;

    // ---- stream in this thread's 16 q and 16 v values (4x LDG.128 each) ----
    float4 q4[4], v4[4];
    #pragma unroll
    for (int i = 0; i < 4; i++) q4[i] = __ldcs((const float4*)(q + base + 4*i));
    #pragma unroll
    for (int i = 0; i < 4; i++) v4[i] = __ldcs((const float4*)(v + base + 4*i));

    // ---- dynamic weights: 3 dots over C; Ww chunks streamed (dedup across halves) ----
    float p0 = 0.0f, p1 = 0.0f, p2 = 0.0f;
    #pragma unroll
    for (int i = 0; i < 4; i++) {
        const float4 w0 = *(const float4*)(Ww + coff + 4*i);
        const float4 w1 = *(const float4*)(Ww + C_DIM + coff + 4*i);
        const float4 w2 = *(const float4*)(Ww + 2*C_DIM + coff + 4*i);
        const float4 qq = q4[i];
        p0 += qq.x*w0.x + qq.y*w0.y + qq.z*w0.z + qq.w*w0.w;
        p1 += qq.x*w1.x + qq.y*w1.y + qq.z*w1.z + qq.w*w1.w;
        p2 += qq.x*w2.x + qq.y*w2.y + qq.z*w2.z + qq.w*w2.w;
    }
    // width-16 butterflies: each half-warp reduces its own row
    #pragma unroll
    for (int off = 8; off > 0; off >>= 1) {
        p0 += __shfl_xor_sync(0xffffffffu, p0, off, 16);
        p1 += __shfl_xor_sync(0xffffffffu, p1, off, 16);
        p2 += __shfl_xor_sync(0xffffffffu, p2, off, 16);
    }
    const float kw0 = p0 + bw[0];
    const float kw1 = p1 + bw[1];
    const float kw2 = p2 + bw[2];

    // ---- conv halos from neighbor lanes within the half-warp ----
    float left  = __shfl_up_sync  (0xffffffffu, v4[3].w, 1, 16);  // v[coff-1]
    float right = __shfl_down_sync(0xffffffffu, v4[0].x, 1, 16);  // v[coff+16]
    if (sub == 0)  left  = 0.0f;   // row edge: zero pad
    if (sub == 15) right = 0.0f;

    // window vv[0..17] = v[coff-1 .. coff+16]
    float vv[18];
    vv[0] = left;
    #pragma unroll
    for (int i = 0; i < 4; i++) {
        vv[4*i + 1] = v4[i].x; vv[4*i + 2] = v4[i].y;
        vv[4*i + 3] = v4[i].z; vv[4*i + 4] = v4[i].w;
    }
    vv[17] = right;

    float o[16];
    #pragma unroll
    for (int i = 0; i < 16; i++)
        o[i] = vv[i]*kw0 + vv[i+1]*kw1 + vv[i+2]*kw2;

    // ---- LayerNorm over C: width-16 butterflies for sum + sumsq ----
    float s1 = 0.0f, s2 = 0.0f;
    #pragma unroll
    for (int i = 0; i < 16; i++) { s1 += o[i]; s2 += o[i]*o[i]; }
    #pragma unroll
    for (int off = 8; off > 0; off >>= 1) {
        s1 += __shfl_xor_sync(0xffffffffu, s1, off, 16);
        s2 += __shfl_xor_sync(0xffffffffu, s2, off, 16);
    }
    const float mu   = s1 * (1.0f / C_DIM);
    const float var  = s2 * (1.0f / C_DIM) - mu * mu;
    const float rstd = rsqrtf(var + LN_EPS);

    // ---- scale/shift + store (gamma/beta dedup across half-warps) ----
    #pragma unroll
    for (int i = 0; i < 4; i++) {
        const float4 g = *(const float4*)(gamma + coff + 4*i);
        const float4 b = *(const float4*)(beta  + coff + 4*i);
        float4 r;
        r.x = (o[4*i+0] - mu) * rstd * g.x + b.x;
        r.y = (o[4*i+1] - mu) * rstd * g.y + b.y;
        r.z = (o[4*i+2] - mu) * rstd * g.z + b.z;
        r.w = (o[4*i+3] - mu) * rstd * g.w + b.w;
        __stcs((float4*)(out + base + 4*i), r);
    }
}

extern "C" void kernel_launch(void* const* d_in, const int* in_sizes, int n_in,
                              void* d_out, int out_size) {
    const float* q     = (const float*)d_in[0];
    const float* v     = (const float*)d_in[1];
    const float* Ww    = (const float*)d_in[2];
    const float* bw    = (const float*)d_in[3];
    const float* gamma = (const float*)d_in[4];
    const float* beta  = (const float*)d_in[5];
    float* out = (float*)d_out;

    const int rows = out_size / C_DIM;            // 102400
    const int ctas = rows / ROWS_PER_CTA;         // 6400
    dydw_atten_kernel<<<ctas, WARPS_PER_CTA * 32>>>(q, v, Ww, bw, gamma, beta, out);
}

// round 7
// speedup vs baseline: 2.1040x; 2.1040x over previous
#include <cuda_runtime.h>

// DyDepthwiseConvAtten: B=1024, N=100, C=256, K=3  (rows = 102400)
// Round 5: R2 structure with INSTRUCTION-COALESCED layout. One warp per row;
// thread t owns channels [4t,4t+4) and [128+4t,128+4t+4), so every
// LDG.128/STG.128 has contiguous lane addresses (4 cache lines, the minimum).
// All reductions via width-32 shfl butterflies; no smem, no barriers.

#define C_DIM 256
#define LN_EPS 1e-5f
#define ROWS_PER_CTA 8          // 8 warps/CTA

__global__ __launch_bounds__(ROWS_PER_CTA * 32, 8)
void dydw_atten_kernel(const float* __restrict__ q,
                       const float* __restrict__ v,
                       const float* __restrict__ Ww,   // [3,256]
                       const float* __restrict__ bw,   // [3]
                       const float* __restrict__ gamma,
                       const float* __restrict__ beta,
                       float* __restrict__ out) {
    const int lane = threadIdx.x & 31;
    const int wrp  = threadIdx.x >> 5;
    const int row  = blockIdx.x * ROWS_PER_CTA + wrp;

    const int    c0   = 4 * lane;           // chunk 0 channels [c0, c0+4)
    const int    c1   = 128 + 4 * lane;     // chunk 1 channels [c1, c1+4)
    const size_t base = (size_t)row * C_DIM;

    // ---- coalesced streaming loads (each LDG.128 = 4 lines exactly) ----
    const float4 q0 = __ldcs((const float4*)(q + base + c0));
    const float4 q1 = __ldcs((const float4*)(q + base + c1));
    const float4 v0 = __ldcs((const float4*)(v + base + c0));
    const float4 v1 = __ldcs((const float4*)(v + base + c1));

    const float4 w00 = *(const float4*)(Ww + c0);
    const float4 w01 = *(const float4*)(Ww + c1);
    const float4 w10 = *(const float4*)(Ww + C_DIM + c0);
    const float4 w11 = *(const float4*)(Ww + C_DIM + c1);
    const float4 w20 = *(const float4*)(Ww + 2*C_DIM + c0);
    const float4 w21 = *(const float4*)(Ww + 2*C_DIM + c1);

    // ---- dynamic weights: 3 dot products over C, warp butterfly ----
    float p0 = q0.x*w00.x + q0.y*w00.y + q0.z*w00.z + q0.w*w00.w
             + q1.x*w01.x + q1.y*w01.y + q1.z*w01.z + q1.w*w01.w;
    float p1 = q0.x*w10.x + q0.y*w10.y + q0.z*w10.z + q0.w*w10.w
             + q1.x*w11.x + q1.y*w11.y + q1.z*w11.z + q1.w*w11.w;
    float p2 = q0.x*w20.x + q0.y*w20.y + q0.z*w20.z + q0.w*w20.w
             + q1.x*w21.x + q1.y*w21.y + q1.z*w21.z + q1.w*w21.w;
    #pragma unroll
    for (int off = 16; off > 0; off >>= 1) {
        p0 += __shfl_xor_sync(0xffffffffu, p0, off);
        p1 += __shfl_xor_sync(0xffffffffu, p1, off);
        p2 += __shfl_xor_sync(0xffffffffu, p2, off);
    }
    const float kw0 = p0 + bw[0];
    const float kw1 = p1 + bw[1];
    const float kw2 = p2 + bw[2];

    // ---- conv halos ----
    // chunk seam broadcasts: channel 127 (lane31.v0.w) and 128 (lane0.v1.x)
    const float ch127 = __shfl_sync(0xffffffffu, v0.w, 31);
    const float ch128 = __shfl_sync(0xffffffffu, v1.x, 0);

    float left0  = __shfl_up_sync  (0xffffffffu, v0.w, 1);  // v[c0-1]
    float right0 = __shfl_down_sync(0xffffffffu, v0.x, 1);  // v[c0+4]
    float left1  = __shfl_up_sync  (0xffffffffu, v1.w, 1);  // v[c1-1]
    float right1 = __shfl_down_sync(0xffffffffu, v1.x, 1);  // v[c1+4]
    if (lane == 0)  { left0 = 0.0f;   left1  = ch127; }     // v[-1]=0, v[127]
    if (lane == 31) { right0 = ch128; right1 = 0.0f;  }     // v[128], v[256]=0

    // ---- depthwise conv (cross-correlation, 'same' padding) ----
    float win0[6] = { left0, v0.x, v0.y, v0.z, v0.w, right0 };
    float win1[6] = { left1, v1.x, v1.y, v1.z, v1.w, right1 };
    float o[8];
    #pragma unroll
    for (int i = 0; i < 4; i++) {
        o[i]     = win0[i]*kw0 + win0[i+1]*kw1 + win0[i+2]*kw2;
        o[i + 4] = win1[i]*kw0 + win1[i+1]*kw1 + win1[i+2]*kw2;
    }

    // ---- LayerNorm: fused sum + sumsq butterflies ----
    float s1 = 0.0f, s2 = 0.0f;
    #pragma unroll
    for (int i = 0; i < 8; i++) { s1 += o[i]; s2 += o[i]*o[i]; }
    #pragma unroll
    for (int off = 16; off > 0; off >>= 1) {
        s1 += __shfl_xor_sync(0xffffffffu, s1, off);
        s2 += __shfl_xor_sync(0xffffffffu, s2, off);
    }
    const float mu   = s1 * (1.0f / C_DIM);
    const float var  = s2 * (1.0f / C_DIM) - mu * mu;
    const float rstd = rsqrtf(var + LN_EPS);

    // ---- scale/shift + coalesced stores ----
    const float4 g0 = *(const float4*)(gamma + c0);
    const float4 g1 = *(const float4*)(gamma + c1);
    const float4 b0 = *(const float4*)(beta  + c0);
    const float4 b1 = *(const float4*)(beta  + c1);

    float4 r0, r1;
    r0.x = (o[0]-mu)*rstd*g0.x + b0.x;
    r0.y = (o[1]-mu)*rstd*g0.y + b0.y;
    r0.z = (o[2]-mu)*rstd*g0.z + b0.z;
    r0.w = (o[3]-mu)*rstd*g0.w + b0.w;
    r1.x = (o[4]-mu)*rstd*g1.x + b1.x;
    r1.y = (o[5]-mu)*rstd*g1.y + b1.y;
    r1.z = (o[6]-mu)*rstd*g1.z + b1.z;
    r1.w = (o[7]-mu)*rstd*g1.w + b1.w;

    __stcs((float4*)(out + base + c0), r0);
    __stcs((float4*)(out + base + c1), r1);
}

extern "C" void kernel_launch(void* const* d_in, const int* in_sizes, int n_in,
                              void* d_out, int out_size) {
    const float* q     = (const float*)d_in[0];
    const float* v     = (const float*)d_in[1];
    const float* Ww    = (const float*)d_in[2];
    const float* bw    = (const float*)d_in[3];
    const float* gamma = (const float*)d_in[4];
    const float* beta  = (const float*)d_in[5];
    float* out = (float*)d_out;

    const int rows = out_size / C_DIM;                  // 102400
    dydw_atten_kernel<<<rows / ROWS_PER_CTA, ROWS_PER_CTA * 32>>>(
        q, v, Ww, bw, gamma, beta, out);
}

// round 9
// speedup vs baseline: 2.1796x; 1.0359x over previous
#include <cuda_runtime.h>

// DyDepthwiseConvAtten: B=1024, N=100, C=256, K=3  (rows = 102400)
// Round 7: coalesced layout (16B lane stride) + 2 rows/warp amortization of
// ALL invariant loads (Ww, gamma, beta, bw), with every streaming load
// front-batched (18 LDG.128 in flight per warp) so low occupancy still
// saturates DRAM. No smem, no barriers; width-32 shfl butterflies with
// 6 (weights) / 4 (LN) independent chains for ILP.

#define C_DIM 256
#define LN_EPS 1e-5f
#define WARPS_PER_CTA 4
#define RPW 2

__global__ __launch_bounds__(WARPS_PER_CTA * 32)
void dydw_atten_kernel(const float* __restrict__ q,
                       const float* __restrict__ v,
                       const float* __restrict__ Ww,   // [3,256]
                       const float* __restrict__ bw,   // [3]
                       const float* __restrict__ gamma,
                       const float* __restrict__ beta,
                       float* __restrict__ out) {
    const int lane  = threadIdx.x & 31;
    const int wrp   = threadIdx.x >> 5;
    const int gwarp = blockIdx.x * WARPS_PER_CTA + wrp;

    const int    c0    = 4 * lane;          // chunk 0: channels [c0, c0+4)
    const int    c1    = 128 + 4 * lane;    // chunk 1: channels [c1, c1+4)
    const size_t baseA = (size_t)(gwarp * RPW)     * C_DIM;
    const size_t baseB = (size_t)(gwarp * RPW + 1) * C_DIM;

    // ---- front-batch ALL streaming loads for both rows (8x LDG.128) ----
    const float4 qa0 = __ldcs((const float4*)(q + baseA + c0));
    const float4 qa1 = __ldcs((const float4*)(q + baseA + c1));
    const float4 va0 = __ldcs((const float4*)(v + baseA + c0));
    const float4 va1 = __ldcs((const float4*)(v + baseA + c1));
    const float4 qb0 = __ldcs((const float4*)(q + baseB + c0));
    const float4 qb1 = __ldcs((const float4*)(q + baseB + c1));
    const float4 vb0 = __ldcs((const float4*)(v + baseB + c0));
    const float4 vb1 = __ldcs((const float4*)(v + baseB + c1));

    // ---- invariants: loaded ONCE per warp, amortized over 2 rows ----
    const float4 w00 = *(const float4*)(Ww + c0);
    const float4 w01 = *(const float4*)(Ww + c1);
    const float4 w10 = *(const float4*)(Ww + C_DIM + c0);
    const float4 w11 = *(const float4*)(Ww + C_DIM + c1);
    const float4 w20 = *(const float4*)(Ww + 2*C_DIM + c0);
    const float4 w21 = *(const float4*)(Ww + 2*C_DIM + c1);
    const float4 g0  = *(const float4*)(gamma + c0);
    const float4 g1  = *(const float4*)(gamma + c1);
    const float4 bt0 = *(const float4*)(beta  + c0);
    const float4 bt1 = *(const float4*)(beta  + c1);
    const float bw0 = bw[0], bw1 = bw[1], bw2 = bw[2];

    // ---- dynamic-weight dots for BOTH rows; 6 independent butterfly chains ----
    float pa0 = qa0.x*w00.x + qa0.y*w00.y + qa0.z*w00.z + qa0.w*w00.w
              + qa1.x*w01.x + qa1.y*w01.y + qa1.z*w01.z + qa1.w*w01.w;
    float pa1 = qa0.x*w10.x + qa0.y*w10.y + qa0.z*w10.z + qa0.w*w10.w
              + qa1.x*w11.x + qa1.y*w11.y + qa1.z*w11.z + qa1.w*w11.w;
    float pa2 = qa0.x*w20.x + qa0.y*w20.y + qa0.z*w20.z + qa0.w*w20.w
              + qa1.x*w21.x + qa1.y*w21.y + qa1.z*w21.z + qa1.w*w21.w;
    float pb0 = qb0.x*w00.x + qb0.y*w00.y + qb0.z*w00.z + qb0.w*w00.w
              + qb1.x*w01.x + qb1.y*w01.y + qb1.z*w01.z + qb1.w*w01.w;
    float pb1 = qb0.x*w10.x + qb0.y*w10.y + qb0.z*w10.z + qb0.w*w10.w
              + qb1.x*w11.x + qb1.y*w11.y + qb1.z*w11.z + qb1.w*w11.w;
    float pb2 = qb0.x*w20.x + qb0.y*w20.y + qb0.z*w20.z + qb0.w*w20.w
              + qb1.x*w21.x + qb1.y*w21.y + qb1.z*w21.z + qb1.w*w21.w;
    #pragma unroll
    for (int off = 16; off > 0; off >>= 1) {
        pa0 += __shfl_xor_sync(0xffffffffu, pa0, off);
        pa1 += __shfl_xor_sync(0xffffffffu, pa1, off);
        pa2 += __shfl_xor_sync(0xffffffffu, pa2, off);
        pb0 += __shfl_xor_sync(0xffffffffu, pb0, off);
        pb1 += __shfl_xor_sync(0xffffffffu, pb1, off);
        pb2 += __shfl_xor_sync(0xffffffffu, pb2, off);
    }
    const float kwa0 = pa0 + bw0, kwa1 = pa1 + bw1, kwa2 = pa2 + bw2;
    const float kwb0 = pb0 + bw0, kwb1 = pb1 + bw1, kwb2 = pb2 + bw2;

    // ---- conv halos, both rows ----
    const float a127 = __shfl_sync(0xffffffffu, va0.w, 31);
    const float a128 = __shfl_sync(0xffffffffu, va1.x, 0);
    const float b127 = __shfl_sync(0xffffffffu, vb0.w, 31);
    const float b128 = __shfl_sync(0xffffffffu, vb1.x, 0);

    float la0 = __shfl_up_sync  (0xffffffffu, va0.w, 1);
    float ra0 = __shfl_down_sync(0xffffffffu, va0.x, 1);
    float la1 = __shfl_up_sync  (0xffffffffu, va1.w, 1);
    float ra1 = __shfl_down_sync(0xffffffffu, va1.x, 1);
    float lb0 = __shfl_up_sync  (0xffffffffu, vb0.w, 1);
    float rb0 = __shfl_down_sync(0xffffffffu, vb0.x, 1);
    float lb1 = __shfl_up_sync  (0xffffffffu, vb1.w, 1);
    float rb1 = __shfl_down_sync(0xffffffffu, vb1.x, 1);
    if (lane == 0)  { la0 = 0.0f; la1 = a127; lb0 = 0.0f; lb1 = b127; }
    if (lane == 31) { ra0 = a128; ra1 = 0.0f; rb0 = b128; rb1 = 0.0f; }

    float oa[8], ob[8];
    {
        float wA0[6] = { la0, va0.x, va0.y, va0.z, va0.w, ra0 };
        float wA1[6] = { la1, va1.x, va1.y, va1.z, va1.w, ra1 };
        float wB0[6] = { lb0, vb0.x, vb0.y, vb0.z, vb0.w, rb0 };
        float wB1[6] = { lb1, vb1.x, vb1.y, vb1.z, vb1.w, rb1 };
        #pragma unroll
        for (int i = 0; i < 4; i++) {
            oa[i]     = wA0[i]*kwa0 + wA0[i+1]*kwa1 + wA0[i+2]*kwa2;
            oa[i + 4] = wA1[i]*kwa0 + wA1[i+1]*kwa1 + wA1[i+2]*kwa2;
            ob[i]     = wB0[i]*kwb0 + wB0[i+1]*kwb1 + wB0[i+2]*kwb2;
            ob[i + 4] = wB1[i]*kwb0 + wB1[i+1]*kwb1 + wB1[i+2]*kwb2;
        }
    }

    // ---- LayerNorm: 4 independent butterfly chains ----
    float sa1 = 0.0f, sa2 = 0.0f, sb1 = 0.0f, sb2 = 0.0f;
    #pragma unroll
    for (int i = 0; i < 8; i++) {
        sa1 += oa[i]; sa2 += oa[i]*oa[i];
        sb1 += ob[i]; sb2 += ob[i]*ob[i];
    }
    #pragma unroll
    for (int off = 16; off > 0; off >>= 1) {
        sa1 += __shfl_xor_sync(0xffffffffu, sa1, off);
        sa2 += __shfl_xor_sync(0xffffffffu, sa2, off);
        sb1 += __shfl_xor_sync(0xffffffffu, sb1, off);
        sb2 += __shfl_xor_sync(0xffffffffu, sb2, off);
    }
    const float muA   = sa1 * (1.0f / C_DIM);
    const float rstdA = rsqrtf(sa2 * (1.0f / C_DIM) - muA*muA + LN_EPS);
    const float muB   = sb1 * (1.0f / C_DIM);
    const float rstdB = rsqrtf(sb2 * (1.0f / C_DIM) - muB*muB + LN_EPS);

    // ---- scale/shift + coalesced streaming stores ----
    float4 r;
    r.x = (oa[0]-muA)*rstdA*g0.x + bt0.x;
    r.y = (oa[1]-muA)*rstdA*g0.y + bt0.y;
    r.z = (oa[2]-muA)*rstdA*g0.z + bt0.z;
    r.w = (oa[3]-muA)*rstdA*g0.w + bt0.w;
    __stcs((float4*)(out + baseA + c0), r);
    r.x = (oa[4]-muA)*rstdA*g1.x + bt1.x;
    r.y = (oa[5]-muA)*rstdA*g1.y + bt1.y;
    r.z = (oa[6]-muA)*rstdA*g1.z + bt1.z;
    r.w = (oa[7]-muA)*rstdA*g1.w + bt1.w;
    __stcs((float4*)(out + baseA + c1), r);
    r.x = (ob[0]-muB)*rstdB*g0.x + bt0.x;
    r.y = (ob[1]-muB)*rstdB*g0.y + bt0.y;
    r.z = (ob[2]-muB)*rstdB*g0.z + bt0.z;
    r.w = (ob[3]-muB)*rstdB*g0.w + bt0.w;
    __stcs((float4*)(out + baseB + c0), r);
    r.x = (ob[4]-muB)*rstdB*g1.x + bt1.x;
    r.y = (ob[5]-muB)*rstdB*g1.y + bt1.y;
    r.z = (ob[6]-muB)*rstdB*g1.z + bt1.z;
    r.w = (ob[7]-muB)*rstdB*g1.w + bt1.w;
    __stcs((float4*)(out + baseB + c1), r);
}

extern "C" void kernel_launch(void* const* d_in, const int* in_sizes, int n_in,
                              void* d_out, int out_size) {
    const float* q     = (const float*)d_in[0];
    const float* v     = (const float*)d_in[1];
    const float* Ww    = (const float*)d_in[2];
    const float* bw    = (const float*)d_in[3];
    const float* gamma = (const float*)d_in[4];
    const float* beta  = (const float*)d_in[5];
    float* out = (float*)d_out;

    const int rows = out_size / C_DIM;                       // 102400
    const int ctas = rows / (RPW * WARPS_PER_CTA);           // 12800
    dydw_atten_kernel<<<ctas, WARPS_PER_CTA * 32>>>(q, v, Ww, bw, gamma, beta, out);
}